// round 14
// baseline (speedup 1.0000x reference)
#include <cuda_runtime.h>

// CTC greedy search — two kernels (proven structure; R13 best: 45.57us).
// R14: K1 ILP — 4 independent max/argmax chains (per float4 component) + 4
// exp-sum accumulators; kills the 32-deep serial dependency chains per row.
//   logits: (T=2048, N=32, V=1024) float32, batch_first = False
//   in_lens: (N,) int (int32 or int64 — detected at runtime)
// Output (float32): [ max_total (N) | paths (T*N, t*N+n) | out_lens (N) ]

#define T_DIM 2048
#define N_DIM 32
#define V_DIM 1024
#define BLANK 1023   // (-1 + V) % V

// Scratch (allocation-free rule: __device__ globals). n-major for kernel2 coalescing.
__device__ int   g_amax[(size_t)T_DIM * N_DIM];
__device__ float g_maxv[(size_t)T_DIM * N_DIM];

// Monotonic (order-preserving) float->uint key and inverse.
__device__ __forceinline__ unsigned fkey(float x) {
    unsigned u = __float_as_uint(x);
    return u ^ (((int)u >> 31) | 0x80000000u);   // pos: flip sign bit; neg: flip all
}
__device__ __forceinline__ float unfkey(unsigned k) {
    unsigned u = (k & 0x80000000u) ? (k ^ 0x80000000u) : ~k;
    return __uint_as_float(u);
}

// ---------------------------------------------------------------------------
// Kernel 1: one warp per (t, n) row of V=1024 logits (~6.8 TB/s).
// ---------------------------------------------------------------------------
__global__ void __launch_bounds__(256) ctc_rowmax_kernel(
    const float* __restrict__ logits, float* __restrict__ out_paths)
{
    const int warp_id = (blockIdx.x * 256 + threadIdx.x) >> 5;  // = t*N + n
    const int lane = threadIdx.x & 31;

    const float4* row =
        reinterpret_cast<const float4*>(logits) + (size_t)warp_id * (V_DIM / 4);

    float4 v[8];
#pragma unroll
    for (int k = 0; k < 8; k++) v[k] = __ldcs(&row[lane + 32 * k]);  // evict-first

    // 4 independent max/argmax chains (x/y/z/w components) — 4x ILP vs the
    // single 32-deep dependent chain. Each chain sees increasing indices, so
    // strict '>' preserves first-occurrence within the chain.
    float mx = v[0].x, my = v[0].y, mz = v[0].z, mw = v[0].w;
    int   ix = (lane)*4, iy = ix + 1, iz = ix + 2, iw = ix + 3;
#pragma unroll
    for (int k = 1; k < 8; k++) {
        const int base = (lane + 32 * k) * 4;
        if (v[k].x > mx) { mx = v[k].x; ix = base;     }
        if (v[k].y > my) { my = v[k].y; iy = base + 1; }
        if (v[k].z > mz) { mz = v[k].z; iz = base + 2; }
        if (v[k].w > mw) { mw = v[k].w; iw = base + 3; }
    }
    // Merge chains with full (value, index) compare — chains interleave
    // indices mod 4, so ties across chains need the index test.
    float m = mx; int mi = ix;
    if (my > m || (my == m && iy < mi)) { m = my; mi = iy; }
    if (mz > m || (mz == m && iz < mi)) { m = mz; mi = iz; }
    if (mw > m || (mw == m && iw < mi)) { m = mw; mi = iw; }

    // Warp max via REDUX on monotonic key; first-occurrence tie-break via
    // REDUX-min over tied lanes' indices.
    const unsigned myKey = fkey(m);
    const unsigned wKey  = __reduce_max_sync(0xffffffffu, myKey);
    mi = __reduce_min_sync(0xffffffffu, (myKey == wKey) ? (unsigned)mi : 0x7fffffffu);
    m  = unfkey(wKey);

    // sum exp(x - m): 4 independent accumulators (breaks 32-deep FADD chain).
    float s0 = 0.f, s1 = 0.f, s2 = 0.f, s3 = 0.f;
#pragma unroll
    for (int k = 0; k < 8; k++) {
        s0 += __expf(v[k].x - m);
        s1 += __expf(v[k].y - m);
        s2 += __expf(v[k].z - m);
        s3 += __expf(v[k].w - m);
    }
    float s = (s0 + s1) + (s2 + s3);
#pragma unroll
    for (int off = 16; off; off >>= 1) s += __shfl_down_sync(0xffffffffu, s, off);

    if (lane == 0) {
        const int t = warp_id >> 5;          // / N_DIM
        const int n = warp_id & 31;
        g_amax[n * T_DIM + t] = mi;
        g_maxv[n * T_DIM + t] = -logf(s);    // max over V of log_softmax
        out_paths[warp_id] = (float)mi;      // masked_scatter default region
    }
}

// ---------------------------------------------------------------------------
// Kernel 2 (single-pass, FROZEN): one 1024-thread block per row n.
// ---------------------------------------------------------------------------
__global__ void __launch_bounds__(1024) ctc_scan_kernel(
    const void* __restrict__ in_lens_raw, float* __restrict__ out)
{
    const int n    = blockIdx.x;
    const int tid  = threadIdx.x;     // 0..1023
    const int lane = tid & 31;
    const int wid  = tid >> 5;        // 0..31

    // dtype-robust in_lens read: values are in [1, T] (never 0). If the buffer
    // is int64 (LE), every high 32-bit word is 0; if int32, word[1] >= 1.
    const int* w32 = (const int*)in_lens_raw;
    const bool is64 = (w32[1] == 0);
    const int L = is64 ? (int)((const long long*)in_lens_raw)[n] : w32[n];

    const int*   a  = g_amax + n * T_DIM;
    const float* mv = g_maxv + n * T_DIM;

    // ---- single vector load of this thread's pair ----
    const int t0 = 2 * tid;
    const int2   aa = reinterpret_cast<const int2*>(a)[tid];
    const float2 mm = reinterpret_cast<const float2*>(mv)[tid];

    // prev element for t0: element t0-1 = previous thread's aa.y.
    int prev = __shfl_up_sync(0xffffffffu, aa.y, 1);
    if (lane == 0) prev = (tid == 0) ? -123 : a[t0 - 1];  // warp boundary / t=0

    const bool k0 = (aa.x != BLANK) && (aa.x != prev) && (t0     < L);
    const bool k1 = (aa.y != BLANK) && (aa.y != aa.x) && (t0 + 1 < L);
    const int  cnt = (int)k0 + (int)k1;

    // ---- max_total partial (fold into the same pass) ----
    float loc = ((t0 < L) ? mm.x : 0.f) + ((t0 + 1 < L) ? mm.y : 0.f);

    // ---- inclusive warp scan of cnt; warp reduce of loc ----
    int inc = cnt;
#pragma unroll
    for (int off = 1; off < 32; off <<= 1) {
        int v = __shfl_up_sync(0xffffffffu, inc, off);
        if (lane >= off) inc += v;
        loc += __shfl_down_sync(0xffffffffu, loc, off);  // lane0 holds warp sum
    }

    __shared__ int   s_wcnt[32];   // exclusive prefix of warp totals (after scan)
    __shared__ float s_wsum[32];
    if (lane == 31) s_wcnt[wid] = inc;      // warp total
    if (lane == 0)  s_wsum[wid] = loc;      // warp sum
    __syncthreads();

    if (wid == 0) {
        // scan 32 warp totals (exclusive), reduce 32 warp sums
        int v = s_wcnt[lane];
        int inc2 = v;
#pragma unroll
        for (int off = 1; off < 32; off <<= 1) {
            int u = __shfl_up_sync(0xffffffffu, inc2, off);
            if (lane >= off) inc2 += u;
        }
        s_wcnt[lane] = inc2 - v;            // exclusive warp offset

        float fs = s_wsum[lane];
#pragma unroll
        for (int off = 16; off; off >>= 1)
            fs += __shfl_down_sync(0xffffffffu, fs, off);

        if (lane == 31) out[N_DIM + (size_t)T_DIM * N_DIM + n] = (float)inc2;  // out_lens
        if (lane == 0)  out[n] = fs;                                           // max_total
    }
    __syncthreads();

    // ---- scatter kept tokens ----
    float* paths = out + N_DIM;
    int pos = s_wcnt[wid] + (inc - cnt);    // exclusive start for this thread
    if (k0) { paths[pos * N_DIM + n] = (float)aa.x; pos++; }
    if (k1) { paths[pos * N_DIM + n] = (float)aa.y; }
}

// ---------------------------------------------------------------------------
extern "C" void kernel_launch(void* const* d_in, const int* in_sizes, int n_in,
                              void* d_out, int out_size)
{
    const float* logits = (const float*)d_in[0];
    const void*  lens   = d_in[1];
    float* out = (float*)d_out;

    (void)in_sizes; (void)n_in; (void)out_size;

    // Kernel 1: T*N = 65536 warps -> 8192 blocks of 256 threads
    ctc_rowmax_kernel<<<(T_DIM * N_DIM) / 8, 256>>>(logits, out + N_DIM);
    // Kernel 2: one 1024-thread block per batch row, single pass
    ctc_scan_kernel<<<N_DIM, 1024>>>(lens, out);
}

// round 15
// speedup vs baseline: 1.0506x; 1.0506x over previous
#include <cuda_runtime.h>

// CTC greedy search — two kernels (R13 structure, best: 45.57us).
// R15: ONLY change vs R13 — 4 exp-sum accumulators (3 extra regs, no index
// chains). R14 showed the max-chain split's register cost regresses; this is
// the isolated cheap half.
//   logits: (T=2048, N=32, V=1024) float32, batch_first = False
//   in_lens: (N,) int (int32 or int64 — detected at runtime)
// Output (float32): [ max_total (N) | paths (T*N, t*N+n) | out_lens (N) ]

#define T_DIM 2048
#define N_DIM 32
#define V_DIM 1024
#define BLANK 1023   // (-1 + V) % V

// Scratch (allocation-free rule: __device__ globals). n-major for kernel2 coalescing.
__device__ int   g_amax[(size_t)T_DIM * N_DIM];
__device__ float g_maxv[(size_t)T_DIM * N_DIM];

// Monotonic (order-preserving) float->uint key and inverse.
__device__ __forceinline__ unsigned fkey(float x) {
    unsigned u = __float_as_uint(x);
    return u ^ (((int)u >> 31) | 0x80000000u);   // pos: flip sign bit; neg: flip all
}
__device__ __forceinline__ float unfkey(unsigned k) {
    unsigned u = (k & 0x80000000u) ? (k ^ 0x80000000u) : ~k;
    return __uint_as_float(u);
}

// ---------------------------------------------------------------------------
// Kernel 1: one warp per (t, n) row of V=1024 logits (~6.8 TB/s).
// ---------------------------------------------------------------------------
__global__ void __launch_bounds__(256) ctc_rowmax_kernel(
    const float* __restrict__ logits, float* __restrict__ out_paths)
{
    const int warp_id = (blockIdx.x * 256 + threadIdx.x) >> 5;  // = t*N + n
    const int lane = threadIdx.x & 31;

    const float4* row =
        reinterpret_cast<const float4*>(logits) + (size_t)warp_id * (V_DIM / 4);

    float4 v[8];
#pragma unroll
    for (int k = 0; k < 8; k++) v[k] = __ldcs(&row[lane + 32 * k]);  // evict-first

    // per-lane max + first-occurrence argmax (indices visited in increasing order)
    float m = -1e30f; int mi = 0;
#pragma unroll
    for (int k = 0; k < 8; k++) {
        const int base = (lane + 32 * k) * 4;
        float x;
        x = v[k].x; if (x > m) { m = x; mi = base;     }
        x = v[k].y; if (x > m) { m = x; mi = base + 1; }
        x = v[k].z; if (x > m) { m = x; mi = base + 2; }
        x = v[k].w; if (x > m) { m = x; mi = base + 3; }
    }

    // Warp max via REDUX on monotonic key; first-occurrence tie-break via
    // REDUX-min over tied lanes' indices.
    const unsigned myKey = fkey(m);
    const unsigned wKey  = __reduce_max_sync(0xffffffffu, myKey);
    mi = __reduce_min_sync(0xffffffffu, (myKey == wKey) ? (unsigned)mi : 0x7fffffffu);
    m  = unfkey(wKey);

    // sum exp(x - m): 4 independent accumulators (breaks 32-deep FADD chain,
    // only +3 registers).
    float s0 = 0.f, s1 = 0.f, s2 = 0.f, s3 = 0.f;
#pragma unroll
    for (int k = 0; k < 8; k++) {
        s0 += __expf(v[k].x - m);
        s1 += __expf(v[k].y - m);
        s2 += __expf(v[k].z - m);
        s3 += __expf(v[k].w - m);
    }
    float s = (s0 + s1) + (s2 + s3);
#pragma unroll
    for (int off = 16; off; off >>= 1) s += __shfl_down_sync(0xffffffffu, s, off);

    if (lane == 0) {
        const int t = warp_id >> 5;          // / N_DIM
        const int n = warp_id & 31;
        g_amax[n * T_DIM + t] = mi;
        g_maxv[n * T_DIM + t] = -logf(s);    // max over V of log_softmax
        out_paths[warp_id] = (float)mi;      // masked_scatter default region
    }
}

// ---------------------------------------------------------------------------
// Kernel 2 (single-pass, FROZEN): one 1024-thread block per row n.
// ---------------------------------------------------------------------------
__global__ void __launch_bounds__(1024) ctc_scan_kernel(
    const void* __restrict__ in_lens_raw, float* __restrict__ out)
{
    const int n    = blockIdx.x;
    const int tid  = threadIdx.x;     // 0..1023
    const int lane = tid & 31;
    const int wid  = tid >> 5;        // 0..31

    // dtype-robust in_lens read: values are in [1, T] (never 0). If the buffer
    // is int64 (LE), every high 32-bit word is 0; if int32, word[1] >= 1.
    const int* w32 = (const int*)in_lens_raw;
    const bool is64 = (w32[1] == 0);
    const int L = is64 ? (int)((const long long*)in_lens_raw)[n] : w32[n];

    const int*   a  = g_amax + n * T_DIM;
    const float* mv = g_maxv + n * T_DIM;

    // ---- single vector load of this thread's pair ----
    const int t0 = 2 * tid;
    const int2   aa = reinterpret_cast<const int2*>(a)[tid];
    const float2 mm = reinterpret_cast<const float2*>(mv)[tid];

    // prev element for t0: element t0-1 = previous thread's aa.y.
    int prev = __shfl_up_sync(0xffffffffu, aa.y, 1);
    if (lane == 0) prev = (tid == 0) ? -123 : a[t0 - 1];  // warp boundary / t=0

    const bool k0 = (aa.x != BLANK) && (aa.x != prev) && (t0     < L);
    const bool k1 = (aa.y != BLANK) && (aa.y != aa.x) && (t0 + 1 < L);
    const int  cnt = (int)k0 + (int)k1;

    // ---- max_total partial (fold into the same pass) ----
    float loc = ((t0 < L) ? mm.x : 0.f) + ((t0 + 1 < L) ? mm.y : 0.f);

    // ---- inclusive warp scan of cnt; warp reduce of loc ----
    int inc = cnt;
#pragma unroll
    for (int off = 1; off < 32; off <<= 1) {
        int v = __shfl_up_sync(0xffffffffu, inc, off);
        if (lane >= off) inc += v;
        loc += __shfl_down_sync(0xffffffffu, loc, off);  // lane0 holds warp sum
    }

    __shared__ int   s_wcnt[32];   // exclusive prefix of warp totals (after scan)
    __shared__ float s_wsum[32];
    if (lane == 31) s_wcnt[wid] = inc;      // warp total
    if (lane == 0)  s_wsum[wid] = loc;      // warp sum
    __syncthreads();

    if (wid == 0) {
        // scan 32 warp totals (exclusive), reduce 32 warp sums
        int v = s_wcnt[lane];
        int inc2 = v;
#pragma unroll
        for (int off = 1; off < 32; off <<= 1) {
            int u = __shfl_up_sync(0xffffffffu, inc2, off);
            if (lane >= off) inc2 += u;
        }
        s_wcnt[lane] = inc2 - v;            // exclusive warp offset

        float fs = s_wsum[lane];
#pragma unroll
        for (int off = 16; off; off >>= 1)
            fs += __shfl_down_sync(0xffffffffu, fs, off);

        if (lane == 31) out[N_DIM + (size_t)T_DIM * N_DIM + n] = (float)inc2;  // out_lens
        if (lane == 0)  out[n] = fs;                                           // max_total
    }
    __syncthreads();

    // ---- scatter kept tokens ----
    float* paths = out + N_DIM;
    int pos = s_wcnt[wid] + (inc - cnt);    // exclusive start for this thread
    if (k0) { paths[pos * N_DIM + n] = (float)aa.x; pos++; }
    if (k1) { paths[pos * N_DIM + n] = (float)aa.y; }
}

// ---------------------------------------------------------------------------
extern "C" void kernel_launch(void* const* d_in, const int* in_sizes, int n_in,
                              void* d_out, int out_size)
{
    const float* logits = (const float*)d_in[0];
    const void*  lens   = d_in[1];
    float* out = (float*)d_out;

    (void)in_sizes; (void)n_in; (void)out_size;

    // Kernel 1: T*N = 65536 warps -> 8192 blocks of 256 threads
    ctc_rowmax_kernel<<<(T_DIM * N_DIM) / 8, 256>>>(logits, out + N_DIM);
    // Kernel 2: one 1024-thread block per batch row, single pass
    ctc_scan_kernel<<<N_DIM, 1024>>>(lens, out);
}

// round 16
// speedup vs baseline: 1.0513x; 1.0007x over previous
#include <cuda_runtime.h>

// CTC greedy search — two kernels (R13/R15 structure, best: 45.57us).
// R16: pack (argmax, maxlogp) into ONE int2 scratch array — K1 epilogue does
// one STG.64 (was 2x scattered STG.32); K2 does one LDG.128 per thread (was
// two dependent 8B loads from arrays 256KB apart).
//   logits: (T=2048, N=32, V=1024) float32, batch_first = False
//   in_lens: (N,) int (int32 or int64 — detected at runtime)
// Output (float32): [ max_total (N) | paths (T*N, t*N+n) | out_lens (N) ]

#define T_DIM 2048
#define N_DIM 32
#define V_DIM 1024
#define BLANK 1023   // (-1 + V) % V

// Scratch (allocation-free rule: __device__ globals). n-major for kernel2
// coalescing. .x = argmax, .y = bitcast(max logp).
__device__ int2 g_pack[(size_t)T_DIM * N_DIM];

// Monotonic (order-preserving) float->uint key and inverse.
__device__ __forceinline__ unsigned fkey(float x) {
    unsigned u = __float_as_uint(x);
    return u ^ (((int)u >> 31) | 0x80000000u);   // pos: flip sign bit; neg: flip all
}
__device__ __forceinline__ float unfkey(unsigned k) {
    unsigned u = (k & 0x80000000u) ? (k ^ 0x80000000u) : ~k;
    return __uint_as_float(u);
}

// ---------------------------------------------------------------------------
// Kernel 1: one warp per (t, n) row of V=1024 logits (~6.8 TB/s).
// ---------------------------------------------------------------------------
__global__ void __launch_bounds__(256) ctc_rowmax_kernel(
    const float* __restrict__ logits, float* __restrict__ out_paths)
{
    const int warp_id = (blockIdx.x * 256 + threadIdx.x) >> 5;  // = t*N + n
    const int lane = threadIdx.x & 31;

    const float4* row =
        reinterpret_cast<const float4*>(logits) + (size_t)warp_id * (V_DIM / 4);

    float4 v[8];
#pragma unroll
    for (int k = 0; k < 8; k++) v[k] = __ldcs(&row[lane + 32 * k]);  // evict-first

    // per-lane max + first-occurrence argmax (indices visited in increasing order)
    float m = -1e30f; int mi = 0;
#pragma unroll
    for (int k = 0; k < 8; k++) {
        const int base = (lane + 32 * k) * 4;
        float x;
        x = v[k].x; if (x > m) { m = x; mi = base;     }
        x = v[k].y; if (x > m) { m = x; mi = base + 1; }
        x = v[k].z; if (x > m) { m = x; mi = base + 2; }
        x = v[k].w; if (x > m) { m = x; mi = base + 3; }
    }

    // Warp max via REDUX on monotonic key; first-occurrence tie-break via
    // REDUX-min over tied lanes' indices.
    const unsigned myKey = fkey(m);
    const unsigned wKey  = __reduce_max_sync(0xffffffffu, myKey);
    mi = __reduce_min_sync(0xffffffffu, (myKey == wKey) ? (unsigned)mi : 0x7fffffffu);
    m  = unfkey(wKey);

    // sum exp(x - m): 4 independent accumulators.
    float s0 = 0.f, s1 = 0.f, s2 = 0.f, s3 = 0.f;
#pragma unroll
    for (int k = 0; k < 8; k++) {
        s0 += __expf(v[k].x - m);
        s1 += __expf(v[k].y - m);
        s2 += __expf(v[k].z - m);
        s3 += __expf(v[k].w - m);
    }
    float s = (s0 + s1) + (s2 + s3);
#pragma unroll
    for (int off = 16; off; off >>= 1) s += __shfl_down_sync(0xffffffffu, s, off);

    if (lane == 0) {
        const int t = warp_id >> 5;          // / N_DIM
        const int n = warp_id & 31;
        g_pack[n * T_DIM + t] = make_int2(mi, __float_as_int(-logf(s)));
        out_paths[warp_id] = (float)mi;      // masked_scatter default region
    }
}

// ---------------------------------------------------------------------------
// Kernel 2 (single-pass): one 1024-thread block per row n. Each thread owns
// 2 consecutive timesteps via ONE int4 load {mi0, mv0, mi1, mv1}.
// ---------------------------------------------------------------------------
__global__ void __launch_bounds__(1024) ctc_scan_kernel(
    const void* __restrict__ in_lens_raw, float* __restrict__ out)
{
    const int n    = blockIdx.x;
    const int tid  = threadIdx.x;     // 0..1023
    const int lane = tid & 31;
    const int wid  = tid >> 5;        // 0..31

    // dtype-robust in_lens read: values are in [1, T] (never 0). If the buffer
    // is int64 (LE), every high 32-bit word is 0; if int32, word[1] >= 1.
    const int* w32 = (const int*)in_lens_raw;
    const bool is64 = (w32[1] == 0);
    const int L = is64 ? (int)((const long long*)in_lens_raw)[n] : w32[n];

    const int2* pk = g_pack + n * T_DIM;

    // ---- ONE 16B load covering both timesteps ----
    const int t0 = 2 * tid;
    const int4 P = reinterpret_cast<const int4*>(pk)[tid];
    const int   a0 = P.x,                  a1 = P.z;
    const float m0 = __int_as_float(P.y),  m1 = __int_as_float(P.w);

    // prev element for t0: previous thread's a1.
    int prev = __shfl_up_sync(0xffffffffu, a1, 1);
    if (lane == 0) prev = (tid == 0) ? -123 : pk[t0 - 1].x;  // warp boundary / t=0

    const bool k0 = (a0 != BLANK) && (a0 != prev) && (t0     < L);
    const bool k1 = (a1 != BLANK) && (a1 != a0)   && (t0 + 1 < L);
    const int  cnt = (int)k0 + (int)k1;

    // ---- max_total partial ----
    float loc = ((t0 < L) ? m0 : 0.f) + ((t0 + 1 < L) ? m1 : 0.f);

    // ---- inclusive warp scan of cnt; warp reduce of loc ----
    int inc = cnt;
#pragma unroll
    for (int off = 1; off < 32; off <<= 1) {
        int v = __shfl_up_sync(0xffffffffu, inc, off);
        if (lane >= off) inc += v;
        loc += __shfl_down_sync(0xffffffffu, loc, off);  // lane0 holds warp sum
    }

    __shared__ int   s_wcnt[32];   // exclusive prefix of warp totals (after scan)
    __shared__ float s_wsum[32];
    if (lane == 31) s_wcnt[wid] = inc;      // warp total
    if (lane == 0)  s_wsum[wid] = loc;      // warp sum
    __syncthreads();

    if (wid == 0) {
        // scan 32 warp totals (exclusive), reduce 32 warp sums
        int v = s_wcnt[lane];
        int inc2 = v;
#pragma unroll
        for (int off = 1; off < 32; off <<= 1) {
            int u = __shfl_up_sync(0xffffffffu, inc2, off);
            if (lane >= off) inc2 += u;
        }
        s_wcnt[lane] = inc2 - v;            // exclusive warp offset

        float fs = s_wsum[lane];
#pragma unroll
        for (int off = 16; off; off >>= 1)
            fs += __shfl_down_sync(0xffffffffu, fs, off);

        if (lane == 31) out[N_DIM + (size_t)T_DIM * N_DIM + n] = (float)inc2;  // out_lens
        if (lane == 0)  out[n] = fs;                                           // max_total
    }
    __syncthreads();

    // ---- scatter kept tokens ----
    float* paths = out + N_DIM;
    int pos = s_wcnt[wid] + (inc - cnt);    // exclusive start for this thread
    if (k0) { paths[pos * N_DIM + n] = (float)a0; pos++; }
    if (k1) { paths[pos * N_DIM + n] = (float)a1; }
}

// ---------------------------------------------------------------------------
extern "C" void kernel_launch(void* const* d_in, const int* in_sizes, int n_in,
                              void* d_out, int out_size)
{
    const float* logits = (const float*)d_in[0];
    const void*  lens   = d_in[1];
    float* out = (float*)d_out;

    (void)in_sizes; (void)n_in; (void)out_size;

    // Kernel 1: T*N = 65536 warps -> 8192 blocks of 256 threads
    ctc_rowmax_kernel<<<(T_DIM * N_DIM) / 8, 256>>>(logits, out + N_DIM);
    // Kernel 2: one 1024-thread block per batch row, single pass
    ctc_scan_kernel<<<N_DIM, 1024>>>(lens, out);
}